// round 12
// baseline (speedup 1.0000x reference)
#include <cuda_runtime.h>
#include <cuda_fp16.h>
#include <math.h>
#include <cstdint>

#define B_ 128
#define N_ 512
#define H_ 512
#define M_ (B_*N_)   // 65536

// ---------------- scratch (static device allocations) ----------------
__device__ float g_gx[B_*3*H_];
__device__ float g_gh[B_*3*H_];
__device__ float g_off_enc[B_*H_];
__device__ float g_off_tgt[B_*H_];
__device__ float g_off_state[B_*H_];
__device__ float g_offP[B_*H_];
__device__ float g_offPt[B_*H_];
__device__ float g_pt[2*M_];            // tgt score partials (n-half 0 / 1)
__device__ float g_pe[2*M_];            // enc score partials
__device__ __half g_Ah[(size_t)M_*H_];  // 64 MB: fp16 static_hidden
__device__ __half g_Wenc[H_*H_];        // fp16 static halves (ld = 512)
__device__ __half g_Wtgt[H_*H_];
__device__ __half g_Wptr[H_*H_];

// ---------------- helpers ----------------
__device__ __forceinline__ uint32_t smem_u32(const void* p) {
    uint32_t a;
    asm("{ .reg .u64 t; cvta.to.shared.u64 t, %1; cvt.u32.u64 %0, t; }" : "=r"(a) : "l"(p));
    return a;
}
__device__ __forceinline__ void cp16(uint32_t dst, const void* src) {
    asm volatile("cp.async.cg.shared.global [%0], [%1], 16;" :: "r"(dst), "l"(src));
}
__device__ __forceinline__ float fast_tanh(float x) {
    float r;
    asm("tanh.approx.f32 %0, %1;" : "=f"(r) : "f"(x));
    return r;
}
__device__ __forceinline__ uint32_t h2u(__half2 h) {
    uint32_t u;
    memcpy(&u, &h, 4);
    return u;
}
__device__ __forceinline__ void ldsm4(uint32_t& r0, uint32_t& r1, uint32_t& r2, uint32_t& r3,
                                      uint32_t addr) {
    asm volatile("ldmatrix.sync.aligned.m8n8.x4.shared.b16 {%0,%1,%2,%3}, [%4];"
                 : "=r"(r0), "=r"(r1), "=r"(r2), "=r"(r3) : "r"(addr));
}
#define MMA_F16(c, a, b) \
    asm volatile("mma.sync.aligned.m16n8k16.row.col.f32.f16.f16.f32 " \
        "{%0,%1,%2,%3}, {%4,%5,%6,%7}, {%8,%9}, {%0,%1,%2,%3};" \
        : "+f"((c)[0]), "+f"((c)[1]), "+f"((c)[2]), "+f"((c)[3]) \
        : "r"((a)[0]), "r"((a)[1]), "r"((a)[2]), "r"((a)[3]), \
          "r"((b)[0]), "r"((b)[1]))

// ---------------- fp32 -> fp16 conversion kernels ----------------
__global__ void f2h_a(const float* __restrict__ in, __half* __restrict__ out)
{
    size_t i = (size_t)blockIdx.x * blockDim.x + threadIdx.x;  // 8 floats per thread
    const float4* in4 = (const float4*)in;
    float4 f0 = in4[2*i], f1 = in4[2*i + 1];
    uint4 u = make_uint4(h2u(__floats2half2_rn(f0.x, f0.y)),
                         h2u(__floats2half2_rn(f0.z, f0.w)),
                         h2u(__floats2half2_rn(f1.x, f1.y)),
                         h2u(__floats2half2_rn(f1.z, f1.w)));
    ((uint4*)out)[i] = u;
}
__global__ void f2h_w3(const float* __restrict__ W0, int l0, __half* __restrict__ o0,
                       const float* __restrict__ W1, int l1, __half* __restrict__ o1,
                       const float* __restrict__ W2, int l2, __half* __restrict__ o2)
{
    const float* W; int ldw; __half* out;
    if (blockIdx.y == 0)      { W = W0; ldw = l0; out = o0; }
    else if (blockIdx.y == 1) { W = W1; ldw = l1; out = o1; }
    else                      { W = W2; ldw = l2; out = o2; }
    int n = blockIdx.x, t = threadIdx.x;  // 64 threads x 8 floats
    const float4* row = (const float4*)(W + (size_t)n * ldw);
    float4 f0 = row[2*t], f1 = row[2*t + 1];
    uint4 u = make_uint4(h2u(__floats2half2_rn(f0.x, f0.y)),
                         h2u(__floats2half2_rn(f0.z, f0.w)),
                         h2u(__floats2half2_rn(f1.x, f1.y)),
                         h2u(__floats2half2_rn(f1.z, f1.w)));
    ((uint4*)(out + (size_t)n * 512))[t] = u;
}
__global__ void zero_out(float* __restrict__ p)
{
    p[blockIdx.x * 512 + threadIdx.x] = 0.f;
}

// ================= tensor-core GEMM (mma.sync f16, f32 accum) + fused tanh-dot ==========
// CTA: 64(M) x 256(N-half), K=512; 512 threads, 16 warps, warp tile 16x64. 2 CTAs/SM.
// ATOMIC=0: writes partial to out0/out1[m].  ATOMIC=1: atomicAdd into out0[m].
template<bool DUAL, bool ATOMIC>
__global__ void __launch_bounds__(512, 2)
tc_mma(const __half* __restrict__ A,     // ld = 512
       const __half* __restrict__ W,     // ld = 512
       const float* __restrict__ off1,
       const float* __restrict__ off2,
       const float* __restrict__ v,
       float* __restrict__ out0,         // partial n-half 0 (or atomic target)
       float* __restrict__ out1)         // partial n-half 1
{
    extern __shared__ uint32_t smu[];
    const uint32_t sbase = smem_u32(smu);
    const int tid = threadIdx.x;
    const int wid = tid >> 5, lane = tid & 31;
    const int wm = wid & 3, wn = wid >> 2;       // warp tile 16(M) x 64(N)
    const int lq = lane & 3, lg = lane >> 2;
    const int m0 = (blockIdx.x >> 1) << 6;
    const int nh = blockIdx.x & 1;
    const int n0 = nh << 8;
    const int b  = m0 >> 9;

    constexpr int SV = 0, SO1 = 256, SO2 = 512, RED = 768;
    constexpr int ABO = 1024, BBO = 4864;
    constexpr int NC = 16;                        // 16 K32-chunks

    float* sv  = (float*)(smu + SV);
    float* so1 = (float*)(smu + SO1);
    float* so2 = (float*)(smu + SO2);
    if (tid < 256) {
        sv[tid]  = v[n0 + tid];
        so1[tid] = off1[b * 512 + n0 + tid];
        if (DUAL) so2[tid] = off2[b * 512 + n0 + tid];
    }

    const int lt = lane >> 3, lj = lane & 7;
    const uint32_t a_lane = ((wm * 16 + (lt & 1) * 8 + lj) * 20 + (lt >> 1) * 4) * 4;
    const uint32_t b_lane = ((wn * 64 + (lt >> 1) * 8 + lj) * 20 + (lt & 1) * 4) * 4;

    auto issue = [&](int c) {
        if (c < NC) {
            const int buf = c % 3;
            const int kc  = c << 5;               // in halves
            const uint32_t ab = sbase + (ABO + buf * 1280) * 4;
            const uint32_t bb = sbase + (BBO + buf * 5120) * 4;
            if (tid < 256) {                      // A: 256 cp16 (64 rows x 4)
                int m = tid >> 2, q = tid & 3;
                cp16(ab + (m * 20 + q * 4) * 4, A + (size_t)(m0 + m) * 512 + kc + q * 8);
            }
#pragma unroll
            for (int j = 0; j < 2; j++) {         // B: 1024 cp16 (256 rows x 4)
                int o = tid + 512 * j, n = o >> 2, q = o & 3;
                cp16(bb + (n * 20 + q * 4) * 4, W + (size_t)(n0 + n) * 512 + kc + q * 8);
            }
        }
        asm volatile("cp.async.commit_group;");
    };

    float acc[8][4];
#pragma unroll
    for (int nb = 0; nb < 8; nb++)
#pragma unroll
        for (int r = 0; r < 4; r++) acc[nb][r] = 0.f;

    issue(0); issue(1);

    for (int c = 0; c < NC; c++) {
        asm volatile("cp.async.wait_group 1;");
        __syncthreads();          // chunk c landed; everyone done computing c-1
        issue(c + 2);

        const int buf = c % 3;
        const uint32_t abuf = sbase + (ABO + buf * 1280) * 4 + a_lane;
        const uint32_t bbuf = sbase + (BBO + buf * 5120) * 4 + b_lane;
#pragma unroll
        for (int ks = 0; ks < 2; ks++) {          // two K=16 steps
            uint32_t afr[4];
            ldsm4(afr[0], afr[1], afr[2], afr[3], abuf + ks * 32);
#pragma unroll
            for (int p = 0; p < 4; p++) {
                uint32_t b0, b1, b2, b3;
                ldsm4(b0, b1, b2, b3, bbuf + (p * 320 + ks * 8) * 4);
                uint32_t bf0[2] = {b0, b1}, bf1[2] = {b2, b3};
                MMA_F16(acc[2*p],     afr, bf0);
                MMA_F16(acc[2*p + 1], afr, bf1);
            }
        }
    }

    // ---- fused epilogue over this warp's 64 columns ----
    float s[2] = {0.f, 0.f};
#pragma unroll
    for (int nb = 0; nb < 8; nb++) {
        int col = wn * 64 + nb * 8 + lq * 2;
#pragma unroll
        for (int r = 0; r < 4; r++) {
            int cc = col + (r & 1);
            float av = acc[nb][r];
            float t1 = fast_tanh(av + so1[cc]);
            float val;
            if (DUAL) {
                float t2 = fast_tanh(av + so2[cc]);
                val = sv[cc] * (5.f * t1 + t2);
            } else {
                val = sv[cc] * t1;
            }
            s[r >> 1] += val;
        }
    }

#pragma unroll
    for (int i = 0; i < 2; i++) {
        s[i] += __shfl_xor_sync(0xffffffffu, s[i], 1);
        s[i] += __shfl_xor_sync(0xffffffffu, s[i], 2);
    }
    float* red = (float*)(smu + RED);  // [64 rows][4 wn]
    __syncthreads();
    if (lq == 0) {
#pragma unroll
        for (int i = 0; i < 2; i++) {
            int row = wm * 16 + i * 8 + lg;
            red[row * 4 + wn] = s[i];
        }
    }
    __syncthreads();
    if (tid < 64) {
        float* rr = red + tid * 4;
        float t = rr[0] + rr[1] + rr[2] + rr[3];
        if (ATOMIC) {
            atomicAdd(out0 + m0 + tid, t);
        } else {
            float* o = nh ? out1 : out0;
            o[m0 + tid] = t;
        }
    }
}

// ---------------- small NT GEMM: warp per output element ----------------
__global__ void small_gemm(const float* __restrict__ A, int lda,
                           const float* __restrict__ W, int ldw,
                           const float* __restrict__ Cinit,
                           float* __restrict__ C, int N)
{
    int m = blockIdx.y;
    int n = blockIdx.x * 8 + (threadIdx.x >> 5);
    int lane = threadIdx.x & 31;
    if (n >= N) return;
    const float* a = A + (size_t)m * lda;
    const float* w = W + (size_t)n * ldw;
    float sum = 0.f;
#pragma unroll
    for (int c = 0; c < 4; c++) {
        int k = c * 128 + lane * 4;
        float4 av = *(const float4*)(a + k);
        float4 wv = *(const float4*)(w + k);
        sum += av.x*wv.x + av.y*wv.y + av.z*wv.z + av.w*wv.w;
    }
#pragma unroll
    for (int o = 16; o; o >>= 1) sum += __shfl_xor_sync(0xffffffffu, sum, o);
    if (lane == 0) {
        float base = Cinit ? Cinit[(size_t)m * N + n] : 0.f;
        C[(size_t)m * N + n] = base + sum;
    }
}

// two independent jobs in one launch (blockIdx.z selects); lda = 512, per-job ldw
__global__ void small_gemm2(const float* __restrict__ A0, const float* __restrict__ W0,
                            int ldw0, float* __restrict__ C0,
                            const float* __restrict__ A1, const float* __restrict__ W1,
                            int ldw1, float* __restrict__ C1, int N)
{
    const float* A = blockIdx.z ? A1 : A0;
    const float* W = blockIdx.z ? W1 : W0;
    const int ldw  = blockIdx.z ? ldw1 : ldw0;
    float* C = blockIdx.z ? C1 : C0;
    int m = blockIdx.y;
    int n = blockIdx.x * 8 + (threadIdx.x >> 5);
    int lane = threadIdx.x & 31;
    if (n >= N) return;
    const float* a = A + (size_t)m * 512;
    const float* w = W + (size_t)n * ldw;
    float sum = 0.f;
#pragma unroll
    for (int c = 0; c < 4; c++) {
        int k = c * 128 + lane * 4;
        float4 av = *(const float4*)(a + k);
        float4 wv = *(const float4*)(w + k);
        sum += av.x*wv.x + av.y*wv.y + av.z*wv.z + av.w*wv.w;
    }
#pragma unroll
    for (int o = 16; o; o >>= 1) sum += __shfl_xor_sync(0xffffffffu, sum, o);
    if (lane == 0) C[(size_t)m * N + n] = sum;
}

// ---------------- GRU gates ----------------
__global__ void gru_gate(const float* __restrict__ bih, const float* __restrict__ bhh,
                         const float* __restrict__ hprev, float* __restrict__ hnew)
{
    int b = blockIdx.x, h = threadIdx.x;
    const float* gx = g_gx + b * 1536;
    const float* gh = g_gh + b * 1536;
    float r = 1.f / (1.f + expf(-(gx[h]     + bih[h]     + gh[h]     + bhh[h])));
    float z = 1.f / (1.f + expf(-(gx[512+h] + bih[512+h] + gh[512+h] + bhh[512+h])));
    float n = tanhf(gx[1024+h] + bih[1024+h] + r * (gh[1024+h] + bhh[1024+h]));
    float hp = hprev[b*512 + h];
    hnew[b*512 + h] = (1.f - z) * n + z * hp;
}

// ======== fused: partial-combine + softmax + context + pointer-offset matvec ========
// block b (512 threads):
//   attn = softmax(s0[b,:] + s1[b,:])
//   ctx[h] = sum_n attn[n] * Ah[b,n,h]            (smem)
//   offOut[b,n] = sum_h ctx[h] * Wc[n*ldw + h] + off_st[b,n]
__global__ void __launch_bounds__(512, 2)
softmax_ctx_off(const float* __restrict__ s0, const float* __restrict__ s1,
                const __half* __restrict__ sh,
                const float* __restrict__ Wc, int ldw,
                const float* __restrict__ off_st,
                float* __restrict__ offOut)
{
    int b = blockIdx.x;
    int h = threadIdx.x; // 512
    __shared__ float ae[512];
    __shared__ float cx[512];
    __shared__ float sm[16];
    int wid = h >> 5, lane = h & 31;

    float val = s0[b * 512 + h] + s1[b * 512 + h];
    float mx = val;
#pragma unroll
    for (int o = 16; o; o >>= 1) mx = fmaxf(mx, __shfl_xor_sync(0xffffffffu, mx, o));
    if (lane == 0) sm[wid] = mx;
    __syncthreads();
    float m = sm[0];
#pragma unroll
    for (int i = 1; i < 16; i++) m = fmaxf(m, sm[i]);
    float e = expf(val - m);
    __syncthreads();
    float ss = e;
#pragma unroll
    for (int o = 16; o; o >>= 1) ss += __shfl_xor_sync(0xffffffffu, ss, o);
    if (lane == 0) sm[wid] = ss;
    __syncthreads();
    float tot = 0.f;
#pragma unroll
    for (int i = 0; i < 16; i++) tot += sm[i];
    ae[h] = e / tot;
    __syncthreads();

    const __half* sp = sh + (size_t)b * 512 * 512 + h;
    float ce = 0.f;
#pragma unroll 4
    for (int n = 0; n < 512; n++)
        ce = fmaf(ae[n], __half2float(sp[(size_t)n * 512]), ce);
    cx[h] = ce;
    __syncthreads();

    // offOut[b, h] = ctx . Wc[h,:] + off_st[b, h]
    const float* w = Wc + (size_t)h * ldw;
    float o = off_st[b * 512 + h];
#pragma unroll 2
    for (int k = 0; k < 512; k += 4) {
        float4 wv = *(const float4*)(w + k);
        o = fmaf(cx[k],   wv.x, o);
        o = fmaf(cx[k+1], wv.y, o);
        o = fmaf(cx[k+2], wv.z, o);
        o = fmaf(cx[k+3], wv.w, o);
    }
    offOut[b * 512 + h] = o;
}

// ---------------- host ----------------
static void* sym_addr(const void* s)
{
    void* p = nullptr;
    cudaGetSymbolAddress(&p, s);
    return p;
}

extern "C" void kernel_launch(void* const* d_in, const int* in_sizes, int n_in,
                              void* d_out, int out_size)
{
    const float* static_h  = (const float*)d_in[0];
    const float* state_emb = (const float*)d_in[1];
    const float* dec_h     = (const float*)d_in[2];
    const float* tgt_h     = (const float*)d_in[3];
    const float* last_hh   = (const float*)d_in[4];
    const float* ptr_v     = (const float*)d_in[5];
    const float* ptr_W     = (const float*)d_in[6];
    const float* enc_v     = (const float*)d_in[7];
    const float* enc_W     = (const float*)d_in[8];
    const float* tgt_v     = (const float*)d_in[9];
    const float* tgt_W     = (const float*)d_in[10];
    const float* w_ih      = (const float*)d_in[11];
    const float* w_hh      = (const float*)d_in[12];
    const float* b_ih      = (const float*)d_in[13];
    const float* b_hh      = (const float*)d_in[14];

    float* out  = (float*)d_out;        // probs: [0, 65536)
    float* hnew = out + 65536;          // new_last_hh: [65536, 131072)

    float* p_gx      = (float*)sym_addr(g_gx);
    float* p_gh      = (float*)sym_addr(g_gh);
    float* p_off_enc = (float*)sym_addr(g_off_enc);
    float* p_off_tgt = (float*)sym_addr(g_off_tgt);
    float* p_off_st  = (float*)sym_addr(g_off_state);
    float* p_offP    = (float*)sym_addr(g_offP);
    float* p_offPt   = (float*)sym_addr(g_offPt);
    float* p_pt      = (float*)sym_addr(g_pt);
    float* p_pe      = (float*)sym_addr(g_pe);
    __half* p_Ah     = (__half*)sym_addr(g_Ah);
    __half* p_Wenc   = (__half*)sym_addr(g_Wenc);
    __half* p_Wtgt   = (__half*)sym_addr(g_Wtgt);
    __half* p_Wptr   = (__half*)sym_addr(g_Wptr);

    constexpr int SMEM_BYTES = 20224 * 4;   // ~79 KB -> 2 CTAs/SM
    static bool init_done = false;
    static cudaStream_t s2, s3;
    static cudaEvent_t evF, evD, evE, evB, evC;
    if (!init_done) {
        cudaFuncSetAttribute((const void*)tc_mma<false, false>,
                             cudaFuncAttributeMaxDynamicSharedMemorySize, SMEM_BYTES);
        cudaFuncSetAttribute((const void*)tc_mma<true, true>,
                             cudaFuncAttributeMaxDynamicSharedMemorySize, SMEM_BYTES);
        cudaStreamCreateWithFlags(&s2, cudaStreamNonBlocking);
        cudaStreamCreateWithFlags(&s3, cudaStreamNonBlocking);
        cudaEventCreateWithFlags(&evF, cudaEventDisableTiming);
        cudaEventCreateWithFlags(&evD, cudaEventDisableTiming);
        cudaEventCreateWithFlags(&evE, cudaEventDisableTiming);
        cudaEventCreateWithFlags(&evB, cudaEventDisableTiming);
        cudaEventCreateWithFlags(&evC, cudaEventDisableTiming);
        init_done = true;
    }

    dim3 g64(64, 128);

    // ---- fork ----
    cudaEventRecord(evF, 0);
    cudaStreamWaitEvent(s2, evF, 0);
    cudaStreamWaitEvent(s3, evF, 0);

    // s3: zero probs + weight conversions + tgt/state offsets
    zero_out<<<128, 512, 0, s3>>>(out);
    f2h_w3<<<dim3(512, 3), 64, 0, s3>>>(tgt_W, 1024, p_Wtgt,
                                        enc_W, 1024, p_Wenc,
                                        ptr_W, 1536, p_Wptr);
    small_gemm2<<<dim3(64, 128, 2), 256, 0, s3>>>(tgt_h, tgt_W + 512, 1024, p_off_tgt,
                                                  state_emb, ptr_W + 1024, 1536, p_off_st,
                                                  512);
    cudaEventRecord(evD, s3);

    // s2: GRU chain + enc offset (hidden under tgt GEMM)
    small_gemm2<<<dim3(192, 128, 2), 256, 0, s2>>>(dec_h, w_ih, 512, p_gx,
                                                   last_hh, w_hh, 512, p_gh, 1536);
    gru_gate<<<128, 512, 0, s2>>>(b_ih, b_hh, last_hh, hnew);
    small_gemm<<<g64, 256, 0, s2>>>(hnew, 512, enc_W + 512, 1024, nullptr, p_off_enc, 512);
    cudaEventRecord(evE, s2);

    // default: A conversion, then big tgt GEMM
    f2h_a<<<16384, 256>>>(static_h, p_Ah);
    cudaStreamWaitEvent(0, evD, 0);
    tc_mma<false, false><<<2048, 512, SMEM_BYTES>>>(p_Ah, p_Wtgt, p_off_tgt, nullptr,
                                                    tgt_v, p_pt, p_pt + 65536);
    cudaEventRecord(evB, 0);

    // s2: tgt postprocessing (fused) overlapped with enc GEMM
    cudaStreamWaitEvent(s2, evB, 0);
    softmax_ctx_off<<<128, 512, 0, s2>>>(p_pt, p_pt + 65536, p_Ah,
                                         ptr_W + 512, 1536, p_off_st, p_offPt);
    cudaEventRecord(evC, s2);

    // default: big enc GEMM + fused enc postprocessing
    cudaStreamWaitEvent(0, evE, 0);
    tc_mma<false, false><<<2048, 512, SMEM_BYTES>>>(p_Ah, p_Wenc, p_off_enc, nullptr,
                                                    enc_v, p_pe, p_pe + 65536);
    softmax_ctx_off<<<128, 512>>>(p_pe, p_pe + 65536, p_Ah,
                                  ptr_W + 512, 1536, p_off_st, p_offP);

    // join + final fused pointer GEMM (atomic partials into zeroed out)
    cudaStreamWaitEvent(0, evC, 0);
    tc_mma<true, true><<<2048, 512, SMEM_BYTES>>>(p_Ah, p_Wptr, p_offP, p_offPt, ptr_v,
                                                  out, nullptr);
}

// round 13
// speedup vs baseline: 1.0915x; 1.0915x over previous
#include <cuda_runtime.h>
#include <cuda_fp16.h>
#include <math.h>
#include <cstdint>

#define B_ 128
#define N_ 512
#define H_ 512
#define M_ (B_*N_)   // 65536

// ---------------- scratch (static device allocations) ----------------
__device__ float g_gx[B_*3*H_];
__device__ float g_gh[B_*3*H_];
__device__ float g_off_enc[B_*H_];
__device__ float g_off_tgt[B_*H_];
__device__ float g_off_state[B_*H_];
__device__ float g_offP[B_*H_];
__device__ float g_offPt[B_*H_];
__device__ float g_pt[2*M_];            // tgt score partials (n-half 0 / 1)
__device__ float g_pe[2*M_];            // enc score partials
__device__ __half g_Ah[(size_t)M_*H_];  // 64 MB: fp16 static_hidden
__device__ __half g_Wenc[H_*H_];        // fp16 static halves (ld = 512)
__device__ __half g_Wtgt[H_*H_];
__device__ __half g_Wptr[H_*H_];

// ---------------- helpers ----------------
__device__ __forceinline__ uint32_t smem_u32(const void* p) {
    uint32_t a;
    asm("{ .reg .u64 t; cvta.to.shared.u64 t, %1; cvt.u32.u64 %0, t; }" : "=r"(a) : "l"(p));
    return a;
}
__device__ __forceinline__ void cp16(uint32_t dst, const void* src) {
    asm volatile("cp.async.cg.shared.global [%0], [%1], 16;" :: "r"(dst), "l"(src));
}
__device__ __forceinline__ float fast_tanh(float x) {
    float r;
    asm("tanh.approx.f32 %0, %1;" : "=f"(r) : "f"(x));
    return r;
}
__device__ __forceinline__ uint32_t h2u(__half2 h) {
    uint32_t u;
    memcpy(&u, &h, 4);
    return u;
}
__device__ __forceinline__ void ldsm4(uint32_t& r0, uint32_t& r1, uint32_t& r2, uint32_t& r3,
                                      uint32_t addr) {
    asm volatile("ldmatrix.sync.aligned.m8n8.x4.shared.b16 {%0,%1,%2,%3}, [%4];"
                 : "=r"(r0), "=r"(r1), "=r"(r2), "=r"(r3) : "r"(addr));
}
#define MMA_F16(c, a, b) \
    asm volatile("mma.sync.aligned.m16n8k16.row.col.f32.f16.f16.f32 " \
        "{%0,%1,%2,%3}, {%4,%5,%6,%7}, {%8,%9}, {%0,%1,%2,%3};" \
        : "+f"((c)[0]), "+f"((c)[1]), "+f"((c)[2]), "+f"((c)[3]) \
        : "r"((a)[0]), "r"((a)[1]), "r"((a)[2]), "r"((a)[3]), \
          "r"((b)[0]), "r"((b)[1]))

// ---------------- fp32 -> fp16 conversion kernels ----------------
__global__ void f2h_a(const float* __restrict__ in, __half* __restrict__ out)
{
    size_t i = (size_t)blockIdx.x * blockDim.x + threadIdx.x;  // 8 floats per thread
    const float4* in4 = (const float4*)in;
    float4 f0 = in4[2*i], f1 = in4[2*i + 1];
    uint4 u = make_uint4(h2u(__floats2half2_rn(f0.x, f0.y)),
                         h2u(__floats2half2_rn(f0.z, f0.w)),
                         h2u(__floats2half2_rn(f1.x, f1.y)),
                         h2u(__floats2half2_rn(f1.z, f1.w)));
    ((uint4*)out)[i] = u;
}
__global__ void f2h_w3(const float* __restrict__ W0, int l0, __half* __restrict__ o0,
                       const float* __restrict__ W1, int l1, __half* __restrict__ o1,
                       const float* __restrict__ W2, int l2, __half* __restrict__ o2)
{
    const float* W; int ldw; __half* out;
    if (blockIdx.y == 0)      { W = W0; ldw = l0; out = o0; }
    else if (blockIdx.y == 1) { W = W1; ldw = l1; out = o1; }
    else                      { W = W2; ldw = l2; out = o2; }
    int n = blockIdx.x, t = threadIdx.x;  // 64 threads x 8 floats
    const float4* row = (const float4*)(W + (size_t)n * ldw);
    float4 f0 = row[2*t], f1 = row[2*t + 1];
    uint4 u = make_uint4(h2u(__floats2half2_rn(f0.x, f0.y)),
                         h2u(__floats2half2_rn(f0.z, f0.w)),
                         h2u(__floats2half2_rn(f1.x, f1.y)),
                         h2u(__floats2half2_rn(f1.z, f1.w)));
    ((uint4*)(out + (size_t)n * 512))[t] = u;
}
__global__ void zero_out(float* __restrict__ p)
{
    p[blockIdx.x * 512 + threadIdx.x] = 0.f;
}

// ================= tensor-core GEMM (mma.sync f16, f32 accum) + fused tanh-dot ==========
// CTA: 64(M) x 256(N-half), K=512; 512 threads, 16 warps, warp tile 16x64. 2 CTAs/SM.
// ATOMIC=0: writes partial to out0/out1[m].  ATOMIC=1: atomicAdd into out0[m].
template<bool DUAL, bool ATOMIC>
__global__ void __launch_bounds__(512, 2)
tc_mma(const __half* __restrict__ A,     // ld = 512
       const __half* __restrict__ W,     // ld = 512
       const float* __restrict__ off1,
       const float* __restrict__ off2,
       const float* __restrict__ v,
       float* __restrict__ out0,         // partial n-half 0 (or atomic target)
       float* __restrict__ out1)         // partial n-half 1
{
    extern __shared__ uint32_t smu[];
    const uint32_t sbase = smem_u32(smu);
    const int tid = threadIdx.x;
    const int wid = tid >> 5, lane = tid & 31;
    const int wm = wid & 3, wn = wid >> 2;       // warp tile 16(M) x 64(N)
    const int lq = lane & 3, lg = lane >> 2;
    const int m0 = (blockIdx.x >> 1) << 6;
    const int nh = blockIdx.x & 1;
    const int n0 = nh << 8;
    const int b  = m0 >> 9;

    constexpr int SV = 0, SO1 = 256, SO2 = 512, RED = 768;
    constexpr int ABO = 1024, BBO = 4864;
    constexpr int NC = 16;                        // 16 K32-chunks

    float* sv  = (float*)(smu + SV);
    float* so1 = (float*)(smu + SO1);
    float* so2 = (float*)(smu + SO2);
    if (tid < 256) {
        sv[tid]  = v[n0 + tid];
        so1[tid] = off1[b * 512 + n0 + tid];
        if (DUAL) so2[tid] = off2[b * 512 + n0 + tid];
    }

    const int lt = lane >> 3, lj = lane & 7;
    const uint32_t a_lane = ((wm * 16 + (lt & 1) * 8 + lj) * 20 + (lt >> 1) * 4) * 4;
    const uint32_t b_lane = ((wn * 64 + (lt >> 1) * 8 + lj) * 20 + (lt & 1) * 4) * 4;

    auto issue = [&](int c) {
        if (c < NC) {
            const int buf = c % 3;
            const int kc  = c << 5;               // in halves
            const uint32_t ab = sbase + (ABO + buf * 1280) * 4;
            const uint32_t bb = sbase + (BBO + buf * 5120) * 4;
            if (tid < 256) {                      // A: 256 cp16 (64 rows x 4)
                int m = tid >> 2, q = tid & 3;
                cp16(ab + (m * 20 + q * 4) * 4, A + (size_t)(m0 + m) * 512 + kc + q * 8);
            }
#pragma unroll
            for (int j = 0; j < 2; j++) {         // B: 1024 cp16 (256 rows x 4)
                int o = tid + 512 * j, n = o >> 2, q = o & 3;
                cp16(bb + (n * 20 + q * 4) * 4, W + (size_t)(n0 + n) * 512 + kc + q * 8);
            }
        }
        asm volatile("cp.async.commit_group;");
    };

    float acc[8][4];
#pragma unroll
    for (int nb = 0; nb < 8; nb++)
#pragma unroll
        for (int r = 0; r < 4; r++) acc[nb][r] = 0.f;

    issue(0); issue(1);

    for (int c = 0; c < NC; c++) {
        asm volatile("cp.async.wait_group 1;");
        __syncthreads();          // chunk c landed; everyone done computing c-1
        issue(c + 2);

        const int buf = c % 3;
        const uint32_t abuf = sbase + (ABO + buf * 1280) * 4 + a_lane;
        const uint32_t bbuf = sbase + (BBO + buf * 5120) * 4 + b_lane;
#pragma unroll
        for (int ks = 0; ks < 2; ks++) {          // two K=16 steps
            uint32_t afr[4];
            ldsm4(afr[0], afr[1], afr[2], afr[3], abuf + ks * 32);
#pragma unroll
            for (int p = 0; p < 4; p++) {
                uint32_t b0, b1, b2, b3;
                ldsm4(b0, b1, b2, b3, bbuf + (p * 320 + ks * 8) * 4);
                uint32_t bf0[2] = {b0, b1}, bf1[2] = {b2, b3};
                MMA_F16(acc[2*p],     afr, bf0);
                MMA_F16(acc[2*p + 1], afr, bf1);
            }
        }
    }

    // ---- fused epilogue over this warp's 64 columns ----
    float s[2] = {0.f, 0.f};
#pragma unroll
    for (int nb = 0; nb < 8; nb++) {
        int col = wn * 64 + nb * 8 + lq * 2;
#pragma unroll
        for (int r = 0; r < 4; r++) {
            int cc = col + (r & 1);
            float av = acc[nb][r];
            float t1 = fast_tanh(av + so1[cc]);
            float val;
            if (DUAL) {
                float t2 = fast_tanh(av + so2[cc]);
                val = sv[cc] * (5.f * t1 + t2);
            } else {
                val = sv[cc] * t1;
            }
            s[r >> 1] += val;
        }
    }

#pragma unroll
    for (int i = 0; i < 2; i++) {
        s[i] += __shfl_xor_sync(0xffffffffu, s[i], 1);
        s[i] += __shfl_xor_sync(0xffffffffu, s[i], 2);
    }
    float* red = (float*)(smu + RED);  // [64 rows][4 wn]
    __syncthreads();
    if (lq == 0) {
#pragma unroll
        for (int i = 0; i < 2; i++) {
            int row = wm * 16 + i * 8 + lg;
            red[row * 4 + wn] = s[i];
        }
    }
    __syncthreads();
    if (tid < 64) {
        float* rr = red + tid * 4;
        float t = rr[0] + rr[1] + rr[2] + rr[3];
        if (ATOMIC) {
            atomicAdd(out0 + m0 + tid, t);
        } else {
            float* o = nh ? out1 : out0;
            o[m0 + tid] = t;
        }
    }
}

// ---------------- small NT GEMM: warp per output element ----------------
__global__ void small_gemm(const float* __restrict__ A, int lda,
                           const float* __restrict__ W, int ldw,
                           const float* __restrict__ Cinit,
                           float* __restrict__ C, int N)
{
    int m = blockIdx.y;
    int n = blockIdx.x * 8 + (threadIdx.x >> 5);
    int lane = threadIdx.x & 31;
    if (n >= N) return;
    const float* a = A + (size_t)m * lda;
    const float* w = W + (size_t)n * ldw;
    float sum = 0.f;
#pragma unroll
    for (int c = 0; c < 4; c++) {
        int k = c * 128 + lane * 4;
        float4 av = *(const float4*)(a + k);
        float4 wv = *(const float4*)(w + k);
        sum += av.x*wv.x + av.y*wv.y + av.z*wv.z + av.w*wv.w;
    }
#pragma unroll
    for (int o = 16; o; o >>= 1) sum += __shfl_xor_sync(0xffffffffu, sum, o);
    if (lane == 0) {
        float base = Cinit ? Cinit[(size_t)m * N + n] : 0.f;
        C[(size_t)m * N + n] = base + sum;
    }
}

// two independent jobs in one launch (blockIdx.z selects); lda = 512, per-job ldw
__global__ void small_gemm2(const float* __restrict__ A0, const float* __restrict__ W0,
                            int ldw0, float* __restrict__ C0,
                            const float* __restrict__ A1, const float* __restrict__ W1,
                            int ldw1, float* __restrict__ C1, int N)
{
    const float* A = blockIdx.z ? A1 : A0;
    const float* W = blockIdx.z ? W1 : W0;
    const int ldw  = blockIdx.z ? ldw1 : ldw0;
    float* C = blockIdx.z ? C1 : C0;
    int m = blockIdx.y;
    int n = blockIdx.x * 8 + (threadIdx.x >> 5);
    int lane = threadIdx.x & 31;
    if (n >= N) return;
    const float* a = A + (size_t)m * 512;
    const float* w = W + (size_t)n * ldw;
    float sum = 0.f;
#pragma unroll
    for (int c = 0; c < 4; c++) {
        int k = c * 128 + lane * 4;
        float4 av = *(const float4*)(a + k);
        float4 wv = *(const float4*)(w + k);
        sum += av.x*wv.x + av.y*wv.y + av.z*wv.z + av.w*wv.w;
    }
#pragma unroll
    for (int o = 16; o; o >>= 1) sum += __shfl_xor_sync(0xffffffffu, sum, o);
    if (lane == 0) C[(size_t)m * N + n] = sum;
}

// ---------------- GRU gates ----------------
__global__ void gru_gate(const float* __restrict__ bih, const float* __restrict__ bhh,
                         const float* __restrict__ hprev, float* __restrict__ hnew)
{
    int b = blockIdx.x, h = threadIdx.x;
    const float* gx = g_gx + b * 1536;
    const float* gh = g_gh + b * 1536;
    float r = 1.f / (1.f + expf(-(gx[h]     + bih[h]     + gh[h]     + bhh[h])));
    float z = 1.f / (1.f + expf(-(gx[512+h] + bih[512+h] + gh[512+h] + bhh[512+h])));
    float n = tanhf(gx[1024+h] + bih[1024+h] + r * (gh[1024+h] + bhh[1024+h]));
    float hp = hprev[b*512 + h];
    hnew[b*512 + h] = (1.f - z) * n + z * hp;
}

// ======== fused: partial-combine + softmax + context + pointer-offset matvec ========
// block b (512 threads):
//   attn = softmax(s0[b,:] + s1[b,:])
//   ctx[h] = sum_n attn[n] * Ah[b,n,h]                       (smem)
//   offOut[b,n] = ctx . Wc[n,:] + off_st[b,n]   (warp-per-output, coalesced)
__global__ void __launch_bounds__(512, 2)
softmax_ctx_off(const float* __restrict__ s0, const float* __restrict__ s1,
                const __half* __restrict__ sh,
                const float* __restrict__ Wc, int ldw,
                const float* __restrict__ off_st,
                float* __restrict__ offOut)
{
    int b = blockIdx.x;
    int h = threadIdx.x; // 512
    __shared__ float ae[512];
    __shared__ float cx[512];
    __shared__ float sm[16];
    int wid = h >> 5, lane = h & 31;

    float val = s0[b * 512 + h] + s1[b * 512 + h];
    float mx = val;
#pragma unroll
    for (int o = 16; o; o >>= 1) mx = fmaxf(mx, __shfl_xor_sync(0xffffffffu, mx, o));
    if (lane == 0) sm[wid] = mx;
    __syncthreads();
    float m = sm[0];
#pragma unroll
    for (int i = 1; i < 16; i++) m = fmaxf(m, sm[i]);
    float e = expf(val - m);
    __syncthreads();
    float ss = e;
#pragma unroll
    for (int o = 16; o; o >>= 1) ss += __shfl_xor_sync(0xffffffffu, ss, o);
    if (lane == 0) sm[wid] = ss;
    __syncthreads();
    float tot = 0.f;
#pragma unroll
    for (int i = 0; i < 16; i++) tot += sm[i];
    ae[h] = e / tot;
    __syncthreads();

    const __half* sp = sh + (size_t)b * 512 * 512 + h;
    float ce = 0.f;
#pragma unroll 4
    for (int n = 0; n < 512; n++)
        ce = fmaf(ae[n], __half2float(sp[(size_t)n * 512]), ce);
    cx[h] = ce;
    __syncthreads();

    // warp-per-output coalesced matvec: warp wid handles outputs [wid*32, wid*32+32)
#pragma unroll 4
    for (int i = 0; i < 32; i++) {
        int n = wid * 32 + i;
        const float* w = Wc + (size_t)n * ldw;
        float sum = 0.f;
#pragma unroll
        for (int c = 0; c < 4; c++) {
            int k = c * 128 + lane * 4;
            float4 wv = *(const float4*)(w + k);
            sum += cx[k]*wv.x + cx[k+1]*wv.y + cx[k+2]*wv.z + cx[k+3]*wv.w;
        }
#pragma unroll
        for (int o = 16; o; o >>= 1) sum += __shfl_xor_sync(0xffffffffu, sum, o);
        if (lane == 0) offOut[b * 512 + n] = sum + off_st[b * 512 + n];
    }
}

// ---------------- host ----------------
static void* sym_addr(const void* s)
{
    void* p = nullptr;
    cudaGetSymbolAddress(&p, s);
    return p;
}

extern "C" void kernel_launch(void* const* d_in, const int* in_sizes, int n_in,
                              void* d_out, int out_size)
{
    const float* static_h  = (const float*)d_in[0];
    const float* state_emb = (const float*)d_in[1];
    const float* dec_h     = (const float*)d_in[2];
    const float* tgt_h     = (const float*)d_in[3];
    const float* last_hh   = (const float*)d_in[4];
    const float* ptr_v     = (const float*)d_in[5];
    const float* ptr_W     = (const float*)d_in[6];
    const float* enc_v     = (const float*)d_in[7];
    const float* enc_W     = (const float*)d_in[8];
    const float* tgt_v     = (const float*)d_in[9];
    const float* tgt_W     = (const float*)d_in[10];
    const float* w_ih      = (const float*)d_in[11];
    const float* w_hh      = (const float*)d_in[12];
    const float* b_ih      = (const float*)d_in[13];
    const float* b_hh      = (const float*)d_in[14];

    float* out  = (float*)d_out;        // probs: [0, 65536)
    float* hnew = out + 65536;          // new_last_hh: [65536, 131072)

    float* p_gx      = (float*)sym_addr(g_gx);
    float* p_gh      = (float*)sym_addr(g_gh);
    float* p_off_enc = (float*)sym_addr(g_off_enc);
    float* p_off_tgt = (float*)sym_addr(g_off_tgt);
    float* p_off_st  = (float*)sym_addr(g_off_state);
    float* p_offP    = (float*)sym_addr(g_offP);
    float* p_offPt   = (float*)sym_addr(g_offPt);
    float* p_pt      = (float*)sym_addr(g_pt);
    float* p_pe      = (float*)sym_addr(g_pe);
    __half* p_Ah     = (__half*)sym_addr(g_Ah);
    __half* p_Wenc   = (__half*)sym_addr(g_Wenc);
    __half* p_Wtgt   = (__half*)sym_addr(g_Wtgt);
    __half* p_Wptr   = (__half*)sym_addr(g_Wptr);

    constexpr int SMEM_BYTES = 20224 * 4;   // ~79 KB -> 2 CTAs/SM
    static bool init_done = false;
    static cudaStream_t s2, s3;
    static cudaEvent_t evF, evD, evE, evB, evC;
    if (!init_done) {
        cudaFuncSetAttribute((const void*)tc_mma<false, false>,
                             cudaFuncAttributeMaxDynamicSharedMemorySize, SMEM_BYTES);
        cudaFuncSetAttribute((const void*)tc_mma<true, true>,
                             cudaFuncAttributeMaxDynamicSharedMemorySize, SMEM_BYTES);
        cudaStreamCreateWithFlags(&s2, cudaStreamNonBlocking);
        cudaStreamCreateWithFlags(&s3, cudaStreamNonBlocking);
        cudaEventCreateWithFlags(&evF, cudaEventDisableTiming);
        cudaEventCreateWithFlags(&evD, cudaEventDisableTiming);
        cudaEventCreateWithFlags(&evE, cudaEventDisableTiming);
        cudaEventCreateWithFlags(&evB, cudaEventDisableTiming);
        cudaEventCreateWithFlags(&evC, cudaEventDisableTiming);
        init_done = true;
    }

    dim3 g64(64, 128);

    // ---- fork ----
    cudaEventRecord(evF, 0);
    cudaStreamWaitEvent(s2, evF, 0);
    cudaStreamWaitEvent(s3, evF, 0);

    // s3: zero probs + weight conversions + tgt/state offsets
    zero_out<<<128, 512, 0, s3>>>(out);
    f2h_w3<<<dim3(512, 3), 64, 0, s3>>>(tgt_W, 1024, p_Wtgt,
                                        enc_W, 1024, p_Wenc,
                                        ptr_W, 1536, p_Wptr);
    small_gemm2<<<dim3(64, 128, 2), 256, 0, s3>>>(tgt_h, tgt_W + 512, 1024, p_off_tgt,
                                                  state_emb, ptr_W + 1024, 1536, p_off_st,
                                                  512);
    cudaEventRecord(evD, s3);

    // s2: GRU chain + enc offset (hidden under tgt GEMM)
    small_gemm2<<<dim3(192, 128, 2), 256, 0, s2>>>(dec_h, w_ih, 512, p_gx,
                                                   last_hh, w_hh, 512, p_gh, 1536);
    gru_gate<<<128, 512, 0, s2>>>(b_ih, b_hh, last_hh, hnew);
    small_gemm<<<g64, 256, 0, s2>>>(hnew, 512, enc_W + 512, 1024, nullptr, p_off_enc, 512);
    cudaEventRecord(evE, s2);

    // default: A conversion, then big tgt GEMM
    f2h_a<<<16384, 256>>>(static_h, p_Ah);
    cudaStreamWaitEvent(0, evD, 0);
    tc_mma<false, false><<<2048, 512, SMEM_BYTES>>>(p_Ah, p_Wtgt, p_off_tgt, nullptr,
                                                    tgt_v, p_pt, p_pt + 65536);
    cudaEventRecord(evB, 0);

    // s2: tgt postprocessing (fused, coalesced) overlapped with enc GEMM
    cudaStreamWaitEvent(s2, evB, 0);
    softmax_ctx_off<<<128, 512, 0, s2>>>(p_pt, p_pt + 65536, p_Ah,
                                         ptr_W + 512, 1536, p_off_st, p_offPt);
    cudaEventRecord(evC, s2);

    // default: big enc GEMM + fused enc postprocessing
    cudaStreamWaitEvent(0, evE, 0);
    tc_mma<false, false><<<2048, 512, SMEM_BYTES>>>(p_Ah, p_Wenc, p_off_enc, nullptr,
                                                    enc_v, p_pe, p_pe + 65536);
    softmax_ctx_off<<<128, 512>>>(p_pe, p_pe + 65536, p_Ah,
                                  ptr_W + 512, 1536, p_off_st, p_offP);

    // join + final fused pointer GEMM (atomic partials into zeroed out)
    cudaStreamWaitEvent(0, evC, 0);
    tc_mma<true, true><<<2048, 512, SMEM_BYTES>>>(p_Ah, p_Wptr, p_offP, p_offPt, ptr_v,
                                                  out, nullptr);
}

// round 14
// speedup vs baseline: 1.2065x; 1.1054x over previous
#include <cuda_runtime.h>
#include <cuda_fp16.h>
#include <math.h>
#include <cstdint>

#define B_ 128
#define N_ 512
#define H_ 512
#define M_ (B_*N_)   // 65536

// ---------------- scratch (static device allocations) ----------------
__device__ float g_gx[B_*3*H_];
__device__ float g_gh[B_*3*H_];
__device__ float g_off_enc[B_*H_];
__device__ float g_off_tgt[B_*H_];
__device__ float g_off_state[B_*H_];
__device__ float g_offP[B_*H_];
__device__ float g_offPt[B_*H_];
__device__ float g_pt[2*M_];            // tgt score partials (n-half 0 / 1)
__device__ float g_pe[2*M_];            // enc score partials
__device__ __half g_Ah[(size_t)M_*H_];  // 64 MB: fp16 static_hidden
__device__ __half g_Wenc[H_*H_];        // fp16 static halves (ld = 512)
__device__ __half g_Wtgt[H_*H_];
__device__ __half g_Wptr[H_*H_];

// ---------------- helpers ----------------
__device__ __forceinline__ uint32_t smem_u32(const void* p) {
    uint32_t a;
    asm("{ .reg .u64 t; cvta.to.shared.u64 t, %1; cvt.u32.u64 %0, t; }" : "=r"(a) : "l"(p));
    return a;
}
__device__ __forceinline__ void cp16(uint32_t dst, const void* src) {
    asm volatile("cp.async.cg.shared.global [%0], [%1], 16;" :: "r"(dst), "l"(src));
}
__device__ __forceinline__ float fast_tanh(float x) {
    float r;
    asm("tanh.approx.f32 %0, %1;" : "=f"(r) : "f"(x));
    return r;
}
__device__ __forceinline__ uint32_t h2u(__half2 h) {
    uint32_t u;
    memcpy(&u, &h, 4);
    return u;
}
__device__ __forceinline__ void ldsm4(uint32_t& r0, uint32_t& r1, uint32_t& r2, uint32_t& r3,
                                      uint32_t addr) {
    asm volatile("ldmatrix.sync.aligned.m8n8.x4.shared.b16 {%0,%1,%2,%3}, [%4];"
                 : "=r"(r0), "=r"(r1), "=r"(r2), "=r"(r3) : "r"(addr));
}
#define MMA_F16(c, a, b) \
    asm volatile("mma.sync.aligned.m16n8k16.row.col.f32.f16.f16.f32 " \
        "{%0,%1,%2,%3}, {%4,%5,%6,%7}, {%8,%9}, {%0,%1,%2,%3};" \
        : "+f"((c)[0]), "+f"((c)[1]), "+f"((c)[2]), "+f"((c)[3]) \
        : "r"((a)[0]), "r"((a)[1]), "r"((a)[2]), "r"((a)[3]), \
          "r"((b)[0]), "r"((b)[1]))

// ---------------- fp32 -> fp16 conversion kernels ----------------
__global__ void f2h_a(const float* __restrict__ in, __half* __restrict__ out)
{
    size_t i = (size_t)blockIdx.x * blockDim.x + threadIdx.x;  // 8 floats per thread
    const float4* in4 = (const float4*)in;
    float4 f0 = in4[2*i], f1 = in4[2*i + 1];
    uint4 u = make_uint4(h2u(__floats2half2_rn(f0.x, f0.y)),
                         h2u(__floats2half2_rn(f0.z, f0.w)),
                         h2u(__floats2half2_rn(f1.x, f1.y)),
                         h2u(__floats2half2_rn(f1.z, f1.w)));
    ((uint4*)out)[i] = u;
}
__global__ void f2h_w3(const float* __restrict__ W0, int l0, __half* __restrict__ o0,
                       const float* __restrict__ W1, int l1, __half* __restrict__ o1,
                       const float* __restrict__ W2, int l2, __half* __restrict__ o2)
{
    const float* W; int ldw; __half* out;
    if (blockIdx.y == 0)      { W = W0; ldw = l0; out = o0; }
    else if (blockIdx.y == 1) { W = W1; ldw = l1; out = o1; }
    else                      { W = W2; ldw = l2; out = o2; }
    int n = blockIdx.x, t = threadIdx.x;  // 64 threads x 8 floats
    const float4* row = (const float4*)(W + (size_t)n * ldw);
    float4 f0 = row[2*t], f1 = row[2*t + 1];
    uint4 u = make_uint4(h2u(__floats2half2_rn(f0.x, f0.y)),
                         h2u(__floats2half2_rn(f0.z, f0.w)),
                         h2u(__floats2half2_rn(f1.x, f1.y)),
                         h2u(__floats2half2_rn(f1.z, f1.w)));
    ((uint4*)(out + (size_t)n * 512))[t] = u;
}
__global__ void zero_out(float* __restrict__ p)
{
    p[blockIdx.x * 512 + threadIdx.x] = 0.f;
}

// ================= tensor-core GEMM (mma.sync f16, f32 accum) + fused tanh-dot ==========
// CTA: 64(M) x 256(N-half), K=512; 512 threads, 16 warps, warp tile 16x64. 2 CTAs/SM.
// ATOMIC=0: writes partial to out0/out1[m].  ATOMIC=1: atomicAdd into out0[m].
template<bool DUAL, bool ATOMIC>
__global__ void __launch_bounds__(512, 2)
tc_mma(const __half* __restrict__ A,     // ld = 512
       const __half* __restrict__ W,     // ld = 512
       const float* __restrict__ off1,
       const float* __restrict__ off2,
       const float* __restrict__ v,
       float* __restrict__ out0,         // partial n-half 0 (or atomic target)
       float* __restrict__ out1)         // partial n-half 1
{
    extern __shared__ uint32_t smu[];
    const uint32_t sbase = smem_u32(smu);
    const int tid = threadIdx.x;
    const int wid = tid >> 5, lane = tid & 31;
    const int wm = wid & 3, wn = wid >> 2;       // warp tile 16(M) x 64(N)
    const int lq = lane & 3, lg = lane >> 2;
    const int m0 = (blockIdx.x >> 1) << 6;
    const int nh = blockIdx.x & 1;
    const int n0 = nh << 8;
    const int b  = m0 >> 9;

    constexpr int SV = 0, SO1 = 256, SO2 = 512, RED = 768;
    constexpr int ABO = 1024, BBO = 4864;
    constexpr int NC = 16;                        // 16 K32-chunks

    float* sv  = (float*)(smu + SV);
    float* so1 = (float*)(smu + SO1);
    float* so2 = (float*)(smu + SO2);
    if (tid < 256) {
        sv[tid]  = v[n0 + tid];
        so1[tid] = off1[b * 512 + n0 + tid];
        if (DUAL) so2[tid] = off2[b * 512 + n0 + tid];
    }

    const int lt = lane >> 3, lj = lane & 7;
    const uint32_t a_lane = ((wm * 16 + (lt & 1) * 8 + lj) * 20 + (lt >> 1) * 4) * 4;
    const uint32_t b_lane = ((wn * 64 + (lt >> 1) * 8 + lj) * 20 + (lt & 1) * 4) * 4;

    auto issue = [&](int c) {
        if (c < NC) {
            const int buf = c % 3;
            const int kc  = c << 5;               // in halves
            const uint32_t ab = sbase + (ABO + buf * 1280) * 4;
            const uint32_t bb = sbase + (BBO + buf * 5120) * 4;
            if (tid < 256) {                      // A: 256 cp16 (64 rows x 4)
                int m = tid >> 2, q = tid & 3;
                cp16(ab + (m * 20 + q * 4) * 4, A + (size_t)(m0 + m) * 512 + kc + q * 8);
            }
#pragma unroll
            for (int j = 0; j < 2; j++) {         // B: 1024 cp16 (256 rows x 4)
                int o = tid + 512 * j, n = o >> 2, q = o & 3;
                cp16(bb + (n * 20 + q * 4) * 4, W + (size_t)(n0 + n) * 512 + kc + q * 8);
            }
        }
        asm volatile("cp.async.commit_group;");
    };

    float acc[8][4];
#pragma unroll
    for (int nb = 0; nb < 8; nb++)
#pragma unroll
        for (int r = 0; r < 4; r++) acc[nb][r] = 0.f;

    issue(0); issue(1);

    for (int c = 0; c < NC; c++) {
        asm volatile("cp.async.wait_group 1;");
        __syncthreads();          // chunk c landed; everyone done computing c-1
        issue(c + 2);

        const int buf = c % 3;
        const uint32_t abuf = sbase + (ABO + buf * 1280) * 4 + a_lane;
        const uint32_t bbuf = sbase + (BBO + buf * 5120) * 4 + b_lane;
#pragma unroll
        for (int ks = 0; ks < 2; ks++) {          // two K=16 steps
            uint32_t afr[4];
            ldsm4(afr[0], afr[1], afr[2], afr[3], abuf + ks * 32);
#pragma unroll
            for (int p = 0; p < 4; p++) {
                uint32_t b0, b1, b2, b3;
                ldsm4(b0, b1, b2, b3, bbuf + (p * 320 + ks * 8) * 4);
                uint32_t bf0[2] = {b0, b1}, bf1[2] = {b2, b3};
                MMA_F16(acc[2*p],     afr, bf0);
                MMA_F16(acc[2*p + 1], afr, bf1);
            }
        }
    }

    // ---- fused epilogue over this warp's 64 columns ----
    float s[2] = {0.f, 0.f};
#pragma unroll
    for (int nb = 0; nb < 8; nb++) {
        int col = wn * 64 + nb * 8 + lq * 2;
#pragma unroll
        for (int r = 0; r < 4; r++) {
            int cc = col + (r & 1);
            float av = acc[nb][r];
            float t1 = fast_tanh(av + so1[cc]);
            float val;
            if (DUAL) {
                float t2 = fast_tanh(av + so2[cc]);
                val = sv[cc] * (5.f * t1 + t2);
            } else {
                val = sv[cc] * t1;
            }
            s[r >> 1] += val;
        }
    }

#pragma unroll
    for (int i = 0; i < 2; i++) {
        s[i] += __shfl_xor_sync(0xffffffffu, s[i], 1);
        s[i] += __shfl_xor_sync(0xffffffffu, s[i], 2);
    }
    float* red = (float*)(smu + RED);  // [64 rows][4 wn]
    __syncthreads();
    if (lq == 0) {
#pragma unroll
        for (int i = 0; i < 2; i++) {
            int row = wm * 16 + i * 8 + lg;
            red[row * 4 + wn] = s[i];
        }
    }
    __syncthreads();
    if (tid < 64) {
        float* rr = red + tid * 4;
        float t = rr[0] + rr[1] + rr[2] + rr[3];
        if (ATOMIC) {
            atomicAdd(out0 + m0 + tid, t);
        } else {
            float* o = nh ? out1 : out0;
            o[m0 + tid] = t;
        }
    }
}

// ---------------- tiled small NT GEMM: 16(M) x 8(N) per block, W row in regs ----------------
// C[m, n] = A[m,:] . W[n,:]  (A ld 512, per-job ldw). Two jobs via blockIdx.z.
// 256 threads = 8 warps; warp w owns column n = bx*8 + w for 16 m-rows.
__global__ void __launch_bounds__(256)
tile_mv(const float* __restrict__ A0, const float* __restrict__ W0, int ldw0,
        float* __restrict__ C0,
        const float* __restrict__ A1, const float* __restrict__ W1, int ldw1,
        float* __restrict__ C1, int N)
{
    __shared__ float As[16][512];
    const float* A = blockIdx.z ? A1 : A0;
    const float* W = blockIdx.z ? W1 : W0;
    const int ldw  = blockIdx.z ? ldw1 : ldw0;
    float* C = blockIdx.z ? C1 : C0;

    const int tid = threadIdx.x;
    const int wid = tid >> 5, lane = tid & 31;
    const int m0 = blockIdx.y << 4;
    const int n  = blockIdx.x * 8 + wid;

    // stage A tile: 16 rows x 512 floats = 2048 float4; 8 per thread (coalesced)
#pragma unroll
    for (int i = 0; i < 8; i++) {
        int idx = tid + 256 * i;            // float4 index
        int row = idx >> 7, col = (idx & 127) << 2;
        *(float4*)&As[row][col] = *(const float4*)(A + (size_t)(m0 + row) * 512 + col);
    }
    __syncthreads();

    // W row once into registers
    float4 wr[4];
    const float* w = W + (size_t)n * ldw;
#pragma unroll
    for (int c = 0; c < 4; c++)
        wr[c] = *(const float4*)(w + lane * 4 + c * 128);

#pragma unroll
    for (int m = 0; m < 16; m++) {
        float s = 0.f;
#pragma unroll
        for (int c = 0; c < 4; c++) {
            float4 a = *(const float4*)&As[m][lane * 4 + c * 128];
            s += a.x * wr[c].x + a.y * wr[c].y + a.z * wr[c].z + a.w * wr[c].w;
        }
#pragma unroll
        for (int o = 16; o; o >>= 1) s += __shfl_xor_sync(0xffffffffu, s, o);
        if (lane == 0) C[(size_t)(m0 + m) * N + n] = s;
    }
}

// ---------------- GRU gates ----------------
__global__ void gru_gate(const float* __restrict__ bih, const float* __restrict__ bhh,
                         const float* __restrict__ hprev, float* __restrict__ hnew)
{
    int b = blockIdx.x, h = threadIdx.x;
    const float* gx = g_gx + b * 1536;
    const float* gh = g_gh + b * 1536;
    float r = 1.f / (1.f + expf(-(gx[h]     + bih[h]     + gh[h]     + bhh[h])));
    float z = 1.f / (1.f + expf(-(gx[512+h] + bih[512+h] + gh[512+h] + bhh[512+h])));
    float n = tanhf(gx[1024+h] + bih[1024+h] + r * (gh[1024+h] + bhh[1024+h]));
    float hp = hprev[b*512 + h];
    hnew[b*512 + h] = (1.f - z) * n + z * hp;
}

// ======== fused: partial-combine + softmax + context + pointer-offset matvec ========
__global__ void __launch_bounds__(512, 2)
softmax_ctx_off(const float* __restrict__ s0, const float* __restrict__ s1,
                const __half* __restrict__ sh,
                const float* __restrict__ Wc, int ldw,
                const float* __restrict__ off_st,
                float* __restrict__ offOut)
{
    int b = blockIdx.x;
    int h = threadIdx.x; // 512
    __shared__ float ae[512];
    __shared__ float cx[512];
    __shared__ float sm[16];
    int wid = h >> 5, lane = h & 31;

    float val = s0[b * 512 + h] + s1[b * 512 + h];
    float mx = val;
#pragma unroll
    for (int o = 16; o; o >>= 1) mx = fmaxf(mx, __shfl_xor_sync(0xffffffffu, mx, o));
    if (lane == 0) sm[wid] = mx;
    __syncthreads();
    float m = sm[0];
#pragma unroll
    for (int i = 1; i < 16; i++) m = fmaxf(m, sm[i]);
    float e = expf(val - m);
    __syncthreads();
    float ss = e;
#pragma unroll
    for (int o = 16; o; o >>= 1) ss += __shfl_xor_sync(0xffffffffu, ss, o);
    if (lane == 0) sm[wid] = ss;
    __syncthreads();
    float tot = 0.f;
#pragma unroll
    for (int i = 0; i < 16; i++) tot += sm[i];
    ae[h] = e / tot;
    __syncthreads();

    const __half* sp = sh + (size_t)b * 512 * 512 + h;
    float ce = 0.f;
#pragma unroll 8
    for (int n = 0; n < 512; n++)
        ce = fmaf(ae[n], __half2float(sp[(size_t)n * 512]), ce);
    cx[h] = ce;
    __syncthreads();

    // warp-per-output coalesced matvec
#pragma unroll 4
    for (int i = 0; i < 32; i++) {
        int n = wid * 32 + i;
        const float* w = Wc + (size_t)n * ldw;
        float sum = 0.f;
#pragma unroll
        for (int c = 0; c < 4; c++) {
            int k = c * 128 + lane * 4;
            float4 wv = *(const float4*)(w + k);
            sum += cx[k]*wv.x + cx[k+1]*wv.y + cx[k+2]*wv.z + cx[k+3]*wv.w;
        }
#pragma unroll
        for (int o = 16; o; o >>= 1) sum += __shfl_xor_sync(0xffffffffu, sum, o);
        if (lane == 0) offOut[b * 512 + n] = sum + off_st[b * 512 + n];
    }
}

// ---------------- host ----------------
static void* sym_addr(const void* s)
{
    void* p = nullptr;
    cudaGetSymbolAddress(&p, s);
    return p;
}

extern "C" void kernel_launch(void* const* d_in, const int* in_sizes, int n_in,
                              void* d_out, int out_size)
{
    const float* static_h  = (const float*)d_in[0];
    const float* state_emb = (const float*)d_in[1];
    const float* dec_h     = (const float*)d_in[2];
    const float* tgt_h     = (const float*)d_in[3];
    const float* last_hh   = (const float*)d_in[4];
    const float* ptr_v     = (const float*)d_in[5];
    const float* ptr_W     = (const float*)d_in[6];
    const float* enc_v     = (const float*)d_in[7];
    const float* enc_W     = (const float*)d_in[8];
    const float* tgt_v     = (const float*)d_in[9];
    const float* tgt_W     = (const float*)d_in[10];
    const float* w_ih      = (const float*)d_in[11];
    const float* w_hh      = (const float*)d_in[12];
    const float* b_ih      = (const float*)d_in[13];
    const float* b_hh      = (const float*)d_in[14];

    float* out  = (float*)d_out;        // probs: [0, 65536)
    float* hnew = out + 65536;          // new_last_hh: [65536, 131072)

    float* p_gx      = (float*)sym_addr(g_gx);
    float* p_gh      = (float*)sym_addr(g_gh);
    float* p_off_enc = (float*)sym_addr(g_off_enc);
    float* p_off_tgt = (float*)sym_addr(g_off_tgt);
    float* p_off_st  = (float*)sym_addr(g_off_state);
    float* p_offP    = (float*)sym_addr(g_offP);
    float* p_offPt   = (float*)sym_addr(g_offPt);
    float* p_pt      = (float*)sym_addr(g_pt);
    float* p_pe      = (float*)sym_addr(g_pe);
    __half* p_Ah     = (__half*)sym_addr(g_Ah);
    __half* p_Wenc   = (__half*)sym_addr(g_Wenc);
    __half* p_Wtgt   = (__half*)sym_addr(g_Wtgt);
    __half* p_Wptr   = (__half*)sym_addr(g_Wptr);

    constexpr int SMEM_BYTES = 20224 * 4;   // ~79 KB -> 2 CTAs/SM
    static bool init_done = false;
    static cudaStream_t s2, s3;
    static cudaEvent_t evF, evD, evE, evB, evC;
    if (!init_done) {
        cudaFuncSetAttribute((const void*)tc_mma<false, false>,
                             cudaFuncAttributeMaxDynamicSharedMemorySize, SMEM_BYTES);
        cudaFuncSetAttribute((const void*)tc_mma<true, true>,
                             cudaFuncAttributeMaxDynamicSharedMemorySize, SMEM_BYTES);
        cudaStreamCreateWithFlags(&s2, cudaStreamNonBlocking);
        cudaStreamCreateWithFlags(&s3, cudaStreamNonBlocking);
        cudaEventCreateWithFlags(&evF, cudaEventDisableTiming);
        cudaEventCreateWithFlags(&evD, cudaEventDisableTiming);
        cudaEventCreateWithFlags(&evE, cudaEventDisableTiming);
        cudaEventCreateWithFlags(&evB, cudaEventDisableTiming);
        cudaEventCreateWithFlags(&evC, cudaEventDisableTiming);
        init_done = true;
    }

    // ---- fork ----
    cudaEventRecord(evF, 0);
    cudaStreamWaitEvent(s2, evF, 0);
    cudaStreamWaitEvent(s3, evF, 0);

    // s3: zero probs + weight conversions + tgt/state offsets (tiled)
    zero_out<<<128, 512, 0, s3>>>(out);
    f2h_w3<<<dim3(512, 3), 64, 0, s3>>>(tgt_W, 1024, p_Wtgt,
                                        enc_W, 1024, p_Wenc,
                                        ptr_W, 1536, p_Wptr);
    tile_mv<<<dim3(64, 8, 2), 256, 0, s3>>>(tgt_h, tgt_W + 512, 1024, p_off_tgt,
                                            state_emb, ptr_W + 1024, 1536, p_off_st, 512);
    cudaEventRecord(evD, s3);

    // s2: GRU chain + enc offset (tiled; hidden under tgt GEMM)
    tile_mv<<<dim3(192, 8, 2), 256, 0, s2>>>(dec_h, w_ih, 512, p_gx,
                                             last_hh, w_hh, 512, p_gh, 1536);
    gru_gate<<<128, 512, 0, s2>>>(b_ih, b_hh, last_hh, hnew);
    tile_mv<<<dim3(64, 8, 1), 256, 0, s2>>>(hnew, enc_W + 512, 1024, p_off_enc,
                                            hnew, enc_W + 512, 1024, p_off_enc, 512);
    cudaEventRecord(evE, s2);

    // default: A conversion, then big tgt GEMM
    f2h_a<<<16384, 256>>>(static_h, p_Ah);
    cudaStreamWaitEvent(0, evD, 0);
    tc_mma<false, false><<<2048, 512, SMEM_BYTES>>>(p_Ah, p_Wtgt, p_off_tgt, nullptr,
                                                    tgt_v, p_pt, p_pt + 65536);
    cudaEventRecord(evB, 0);

    // s2: tgt postprocessing (fused, coalesced) overlapped with enc GEMM
    cudaStreamWaitEvent(s2, evB, 0);
    softmax_ctx_off<<<128, 512, 0, s2>>>(p_pt, p_pt + 65536, p_Ah,
                                         ptr_W + 512, 1536, p_off_st, p_offPt);
    cudaEventRecord(evC, s2);

    // default: big enc GEMM + fused enc postprocessing
    cudaStreamWaitEvent(0, evE, 0);
    tc_mma<false, false><<<2048, 512, SMEM_BYTES>>>(p_Ah, p_Wenc, p_off_enc, nullptr,
                                                    enc_v, p_pe, p_pe + 65536);
    softmax_ctx_off<<<128, 512>>>(p_pe, p_pe + 65536, p_Ah,
                                  ptr_W + 512, 1536, p_off_st, p_offP);

    // join + final fused pointer GEMM (atomic partials into zeroed out)
    cudaStreamWaitEvent(0, evC, 0);
    tc_mma<true, true><<<2048, 512, SMEM_BYTES>>>(p_Ah, p_Wptr, p_offP, p_offPt, ptr_v,
                                                  out, nullptr);
}